// round 4
// baseline (speedup 1.0000x reference)
#include <cuda_runtime.h>
#include <cstdint>

#define S_LEN 101
#define BATCH 2048
#define HID 200
#define DIN 120
#define DOUT 12
#define M_TOTAL (S_LEN * BATCH)   // 206848

// Scratch (no allocations allowed -> __device__ globals)
// b-major layouts: cur[b][t][n], spk2[b][t][w]
__device__ float    g_cur[(size_t)M_TOTAL * HID];     // ~165 MB
__device__ unsigned g_spk2[(size_t)M_TOTAL * 7];      // ~5.8 MB

// ---------- packed f32x2 helpers ----------
__device__ __forceinline__ unsigned long long pack2(float lo, float hi) {
    unsigned long long r;
    asm("mov.b64 %0, {%1,%2};" : "=l"(r) : "f"(lo), "f"(hi));
    return r;
}
__device__ __forceinline__ void unpack2(unsigned long long v, float& lo, float& hi) {
    asm("mov.b64 {%0,%1}, %2;" : "=f"(lo), "=f"(hi) : "l"(v));
}
__device__ __forceinline__ unsigned long long fma2(unsigned long long a,
                                                   unsigned long long b,
                                                   unsigned long long c) {
    unsigned long long d;
    asm("fma.rn.f32x2 %0, %1, %2, %3;" : "=l"(d) : "l"(a), "l"(b), "l"(c));
    return d;
}

// ================= Kernel 1: CUR1 = X @ W1 + b1 =================
// M = B*S (row = b*101+t, b-major), K=120, N=200. 800 threads = 25 warps.
// Warp w owns 8 consecutive cols (B loads broadcast within warp, 1 wf).
// Lane owns rows lane+32*i, i<4 (A LDS.128 conflict-free with stride 124).
// 206848 = 128*1616 exactly -> no row guards.
#define G1_BM 128
#define G1_TM 4
#define G1_THREADS 800
#define G1_ASTR 124                               // padded A row stride (floats)
#define G1_SMEM ((G1_BM * G1_ASTR + DIN * HID) * 4)   // 159488 B

__global__ __launch_bounds__(G1_THREADS, 1)
void gemm1_kernel(const float* __restrict__ x,
                  const float* __restrict__ W1,
                  const float* __restrict__ b1) {
    extern __shared__ float smem[];
    float* As = smem;                      // [128][124]
    float* Bs = smem + G1_BM * G1_ASTR;    // [120][200]
    const int tid  = threadIdx.x;
    const int warp = tid >> 5;
    const int lane = tid & 31;
    const int c0   = warp * 8;             // this warp's first output column

    for (int i = tid; i < DIN * HID; i += G1_THREADS) Bs[i] = W1[i];

    const int ntiles = M_TOTAL / G1_BM;    // 1616 exact
    for (int tile = blockIdx.x; tile < ntiles; tile += gridDim.x) {
        __syncthreads();   // protect As (prev readers) & Bs visibility (1st iter)
        const int row0 = tile * G1_BM;
        for (int i = tid; i < G1_BM * DIN; i += G1_THREADS) {
            int r = i / DIN, k = i - r * DIN;
            int row = row0 + r;
            int b = row / S_LEN, t = row - b * S_LEN;
            int c = k / 40,      m = k - c * 40;
            As[r * G1_ASTR + k] = x[((b * 3 + c) * S_LEN + t) * 40 + m];
        }
        __syncthreads();

        // acc[i][j] = f32x2 over cols (c0+2j, c0+2j+1), row lane+32i; init bias
        unsigned long long acc[G1_TM][4];
        {
            float4 q0 = *(const float4*)(b1 + c0);
            float4 q1 = *(const float4*)(b1 + c0 + 4);
            unsigned long long bj[4] = { pack2(q0.x, q0.y), pack2(q0.z, q0.w),
                                         pack2(q1.x, q1.y), pack2(q1.z, q1.w) };
            #pragma unroll
            for (int i = 0; i < G1_TM; i++)
                #pragma unroll
                for (int j = 0; j < 4; j++) acc[i][j] = bj[j];
        }

        for (int k0 = 0; k0 < DIN; k0 += 4) {
            float4 av[G1_TM];
            #pragma unroll
            for (int i = 0; i < G1_TM; i++)
                av[i] = *(const float4*)(As + (lane + 32 * i) * G1_ASTR + k0);

            #pragma unroll
            for (int kk = 0; kk < 4; kk++) {
                const float* brow = Bs + (k0 + kk) * HID + c0;   // broadcast
                float4 q0 = *(const float4*)brow;
                float4 q1 = *(const float4*)(brow + 4);
                unsigned long long bf[4] = { pack2(q0.x, q0.y), pack2(q0.z, q0.w),
                                             pack2(q1.x, q1.y), pack2(q1.z, q1.w) };
                #pragma unroll
                for (int i = 0; i < G1_TM; i++) {
                    float a = (kk == 0) ? av[i].x : (kk == 1) ? av[i].y
                            : (kk == 2) ? av[i].z : av[i].w;
                    unsigned long long a2 = pack2(a, a);
                    #pragma unroll
                    for (int j = 0; j < 4; j++)
                        acc[i][j] = fma2(a2, bf[j], acc[i][j]);
                }
            }
        }

        #pragma unroll
        for (int i = 0; i < G1_TM; i++) {
            int row = row0 + lane + 32 * i;
            float* op = g_cur + (size_t)row * HID + c0;
            float l0, h0, l1, h1, l2, h2, l3, h3;
            unpack2(acc[i][0], l0, h0); unpack2(acc[i][1], l1, h1);
            unpack2(acc[i][2], l2, h2); unpack2(acc[i][3], l3, h3);
            float4 s0 = make_float4(l0, h0, l1, h1);
            float4 s1 = make_float4(l2, h2, l3, h3);
            *(float4*)op       = s0;
            *(float4*)(op + 4) = s1;
        }
    }
}

// ================= LIF kernels =================
// 4 independent groups of 224 threads (7 warps) per CTA, named barriers per
// group. Sparse scan via per-warp index list (latency-tolerant batched loads).
#define L_GROUPS 4
#define GW 224
#define L_THREADS (L_GROUPS * GW)               // 896
#define W_SMEM ((201 * HID + 24) * 4)           // Ws[201][200] + slack; row 200 = zeros

__device__ __forceinline__ void group_bar(int grp) {
    asm volatile("bar.sync %0, %1;" :: "r"(grp + 1), "r"(GW) : "memory");
}

// Build spike index list (warp-redundant, no cross-warp sync). words[0..6]
// identical across lanes. Pads count to multiple of 4 with index HID (zero row).
__device__ __forceinline__ int build_list(const unsigned* words, int* wlist, int lane) {
    int base = 0;
    const unsigned lmask = (1u << lane) - 1u;
    #pragma unroll
    for (int w = 0; w < 7; w++) {
        unsigned word = words[w];
        if (word & (1u << lane))
            wlist[base + __popc(word & lmask)] = (w << 5) + lane;
        base += __popc(word);
    }
    int cnt4 = (base + 3) & ~3;
    if (lane < cnt4 - base) wlist[base + lane] = HID;   // zero-row pad
    __syncwarp();
    return cnt4;
}

// Batched sparse row-sum: 4 independent LDS per iter, 4 accumulators.
__device__ __forceinline__ float list_scan(const int* wlist, int cnt4,
                                           const float* Ws, int n, float bias) {
    float a0 = bias, a1 = 0.f, a2 = 0.f, a3 = 0.f;
    for (int i = 0; i < cnt4; i += 4) {
        int4 id = *(const int4*)(wlist + i);    // broadcast
        float w0 = Ws[id.x * HID + n];
        float w1 = Ws[id.y * HID + n];
        float w2 = Ws[id.z * HID + n];
        float w3 = Ws[id.w * HID + n];
        a0 += w0; a1 += w1; a2 += w2; a3 += w3;
    }
    return (a0 + a1) + (a2 + a3);
}

// ------- Kernel 2: LIF1 + sparse GEMM2 + LIF2 -> spk2 bits -------
__global__ __launch_bounds__(L_THREADS, 1)
void lif2_kernel(const float* __restrict__ W2, const float* __restrict__ b2) {
    extern __shared__ float smem[];
    float* Ws = smem;                                  // [201][200], row 200 = 0
    __shared__ unsigned sw[2][L_GROUPS][8];
    __shared__ __align__(16) int lists[L_GROUPS][7][208];
    const int tid = threadIdx.x;
    for (int i = tid; i < HID * HID; i += L_THREADS) Ws[i] = W2[i];
    for (int i = tid; i < GW; i += L_THREADS) Ws[HID * HID + i] = 0.f;  // zero row

    const int  grp  = tid / GW;
    const int  n    = tid - grp * GW;      // 0..223, active n<200
    const int  lane = n & 31;
    const int  wig  = n >> 5;              // warp in group 0..6
    const bool nv   = (n < HID);
    const float bias = nv ? b2[n] : 0.f;
    int* wlist = lists[grp][wig];
    __syncthreads();

    for (int b0 = blockIdx.x * L_GROUPS; b0 < BATCH; b0 += gridDim.x * L_GROUPS) {
        const int  b    = b0 + grp;
        const bool bact = (b < BATCH);
        float v1 = 0.f, v2 = 0.f;
        const int brd = bact ? b : 0;                      // safe read base
        const float*  curp = g_cur  + (size_t)brd * S_LEN * HID + (nv ? n : 0);
        unsigned*     spk  = g_spk2 + (size_t)brd * S_LEN * 7;

        const int P = 4;
        float buf[P];
        #pragma unroll
        for (int i = 0; i < P; i++) buf[i] = curp[(size_t)i * HID];

        for (int t = 0; t < S_LEN; t++) {
            float cur = buf[t & (P - 1)];
            int tp = t + P; if (tp > S_LEN - 1) tp = S_LEN - 1;
            buf[t & (P - 1)] = curp[(size_t)tp * HID];     // prefetch (indep of v)

            v1 = 0.5f * (v1 + cur);
            bool s1 = nv && (v1 >= 1.0f);
            if (s1) v1 = 0.f;
            unsigned bal = __ballot_sync(0xffffffffu, s1);
            if (lane == 0) sw[t & 1][grp][wig] = bal;
            group_bar(grp);

            int cnt4 = build_list(sw[t & 1][grp], wlist, lane);
            float acc = list_scan(wlist, cnt4, Ws, n, bias);

            v2 = 0.5f * (v2 + acc);
            bool s2 = nv && (v2 >= 1.0f);
            if (s2) v2 = 0.f;
            unsigned bal2 = __ballot_sync(0xffffffffu, s2);
            if (bact && lane == 0) spk[(size_t)t * 7 + wig] = bal2;
        }
    }
}

// ------- Kernel 3: sparse GEMM3 + LIF3 + fused readout/log_softmax -------
__global__ __launch_bounds__(L_THREADS, 1)
void lif3_kernel(const float* __restrict__ W3, const float* __restrict__ b3,
                 const float* __restrict__ Wr, const float* __restrict__ br,
                 float* __restrict__ out) {
    extern __shared__ float smem[];
    float* Ws = smem;
    __shared__ float cnt_sm[L_GROUPS][GW];
    __shared__ __align__(16) int lists[L_GROUPS][7][208];
    const int tid = threadIdx.x;
    for (int i = tid; i < HID * HID; i += L_THREADS) Ws[i] = W3[i];
    for (int i = tid; i < GW; i += L_THREADS) Ws[HID * HID + i] = 0.f;

    const int  grp  = tid / GW;
    const int  n    = tid - grp * GW;
    const int  lane = n & 31;
    const int  wig  = n >> 5;
    const bool nv   = (n < HID);
    const float bias = nv ? b3[n] : 0.f;
    int* wlist = lists[grp][wig];
    __syncthreads();

    for (int b0 = blockIdx.x * L_GROUPS; b0 < BATCH; b0 += gridDim.x * L_GROUPS) {
        const int b = b0 + grp;
        if (b >= BATCH) continue;          // group-uniform; no CTA-wide barriers below
        float v3 = 0.f;
        int cnt = 0;
        const unsigned* sp = g_spk2 + (size_t)b * S_LEN * 7;

        unsigned curm[7];
        #pragma unroll
        for (int w = 0; w < 7; w++) curm[w] = __ldg(sp + w);

        for (int t = 0; t < S_LEN; t++) {
            unsigned nxtm[7];
            const unsigned* spn = sp + (size_t)((t + 1 < S_LEN) ? t + 1 : t) * 7;
            #pragma unroll
            for (int w = 0; w < 7; w++) nxtm[w] = __ldg(spn + w);   // prefetch

            int cnt4 = build_list(curm, wlist, lane);
            float acc = list_scan(wlist, cnt4, Ws, n, bias);

            v3 = 0.5f * (v3 + acc);
            if (v3 >= 1.0f) { v3 = 0.f; cnt++; }
            #pragma unroll
            for (int w = 0; w < 7; w++) curm[w] = nxtm[w];
        }
        cnt_sm[grp][n] = nv ? (float)cnt : 0.f;
        group_bar(grp);

        if (wig == 0) {                    // warp 0 of group: readout for this b
            float o = -3.0e38f;
            if (lane < DOUT) {
                float acc = 0.f;
                #pragma unroll 4
                for (int k = 0; k < HID; k++)
                    acc += cnt_sm[grp][k] * Wr[k * DOUT + lane];
                o = acc * (1.0f / 101.0f) + br[lane];
            }
            float m = o;
            #pragma unroll
            for (int off = 16; off; off >>= 1)
                m = fmaxf(m, __shfl_xor_sync(0xffffffffu, m, off));
            float e = (lane < DOUT) ? expf(o - m) : 0.f;
            float ssum = e;
            #pragma unroll
            for (int off = 16; off; off >>= 1)
                ssum += __shfl_xor_sync(0xffffffffu, ssum, off);
            if (lane < DOUT) out[b * DOUT + lane] = (o - m) - logf(ssum);
        }
        group_bar(grp);                    // protect cnt_sm before next b iter
    }
}

// ================= launch ====================================================
extern "C" void kernel_launch(void* const* d_in, const int* in_sizes, int n_in,
                              void* d_out, int out_size) {
    const float* x  = (const float*)d_in[0];
    const float* W1 = (const float*)d_in[1];
    const float* b1 = (const float*)d_in[2];
    const float* W2 = (const float*)d_in[3];
    const float* b2 = (const float*)d_in[4];
    const float* W3 = (const float*)d_in[5];
    const float* b3 = (const float*)d_in[6];
    const float* Wr = (const float*)d_in[7];
    const float* br = (const float*)d_in[8];
    float* out = (float*)d_out;

    cudaFuncSetAttribute(gemm1_kernel, cudaFuncAttributeMaxDynamicSharedMemorySize, G1_SMEM);
    cudaFuncSetAttribute(lif2_kernel,  cudaFuncAttributeMaxDynamicSharedMemorySize, W_SMEM);
    cudaFuncSetAttribute(lif3_kernel,  cudaFuncAttributeMaxDynamicSharedMemorySize, W_SMEM);

    const int grid = 148;   // 1 CTA/SM (smem-bound); persistent stride loops

    gemm1_kernel<<<grid, G1_THREADS, G1_SMEM>>>(x, W1, b1);
    lif2_kernel <<<grid, L_THREADS,  W_SMEM>>>(W2, b2);
    lif3_kernel <<<grid, L_THREADS,  W_SMEM>>>(W3, b3, Wr, br, out);
}

// round 5
// speedup vs baseline: 1.7768x; 1.7768x over previous
#include <cuda_runtime.h>
#include <cstdint>

#define S_LEN 101
#define BATCH 2048
#define HID 200
#define DIN 120
#define DOUT 12
#define M_TOTAL (S_LEN * BATCH)   // 206848

// Scratch (no allocations allowed -> __device__ globals)
// b-major layouts: cur[b][t][n], spk2[b][t][w] (8 mask words per t)
__device__ float    g_cur[(size_t)M_TOTAL * HID];     // ~165 MB
__device__ unsigned g_spk2[(size_t)M_TOTAL * 8];      // ~6.6 MB

typedef unsigned long long ull;

// ---------- packed f32x2 helpers ----------
__device__ __forceinline__ ull pack2(float lo, float hi) {
    ull r;
    asm("mov.b64 %0, {%1,%2};" : "=l"(r) : "f"(lo), "f"(hi));
    return r;
}
__device__ __forceinline__ void unpack2(ull v, float& lo, float& hi) {
    asm("mov.b64 {%0,%1}, %2;" : "=f"(lo), "=f"(hi) : "l"(v));
}
__device__ __forceinline__ ull fma2(ull a, ull b, ull c) {
    ull d;
    asm("fma.rn.f32x2 %0, %1, %2, %3;" : "=l"(d) : "l"(a), "l"(b), "l"(c));
    return d;
}
__device__ __forceinline__ ull add2(ull a, ull b) {
    ull d;
    asm("add.rn.f32x2 %0, %1, %2;" : "=l"(d) : "l"(a), "l"(b));
    return d;
}

// ================= Kernel 1: CUR1 = X @ W1 + b1 (unchanged, 277us) ==========
#define G1_BM 128
#define G1_TM 4
#define G1_THREADS 800
#define G1_ASTR 124
#define G1_SMEM ((G1_BM * G1_ASTR + DIN * HID) * 4)   // 159488 B

__global__ __launch_bounds__(G1_THREADS, 1)
void gemm1_kernel(const float* __restrict__ x,
                  const float* __restrict__ W1,
                  const float* __restrict__ b1) {
    extern __shared__ float smem[];
    float* As = smem;                      // [128][124]
    float* Bs = smem + G1_BM * G1_ASTR;    // [120][200]
    const int tid  = threadIdx.x;
    const int warp = tid >> 5;
    const int lane = tid & 31;
    const int c0   = warp * 8;

    for (int i = tid; i < DIN * HID; i += G1_THREADS) Bs[i] = W1[i];

    ull bj[4];
    {
        float4 q0 = *(const float4*)(b1 + c0);
        float4 q1 = *(const float4*)(b1 + c0 + 4);
        bj[0] = pack2(q0.x, q0.y); bj[1] = pack2(q0.z, q0.w);
        bj[2] = pack2(q1.x, q1.y); bj[3] = pack2(q1.z, q1.w);
    }

    const int ntiles = M_TOTAL / G1_BM;    // 1616 exact
    for (int tile = blockIdx.x; tile < ntiles; tile += gridDim.x) {
        __syncthreads();
        const int row0 = tile * G1_BM;
        for (int i = tid; i < G1_BM * DIN; i += G1_THREADS) {
            int r = i / DIN, k = i - r * DIN;
            int row = row0 + r;
            int b = row / S_LEN, t = row - b * S_LEN;
            int c = k / 40,      m = k - c * 40;
            As[r * G1_ASTR + k] = x[((b * 3 + c) * S_LEN + t) * 40 + m];
        }
        __syncthreads();

        ull acc[G1_TM][4];
        #pragma unroll
        for (int i = 0; i < G1_TM; i++)
            #pragma unroll
            for (int j = 0; j < 4; j++) acc[i][j] = bj[j];

        for (int k0 = 0; k0 < DIN; k0 += 4) {
            float4 av[G1_TM];
            #pragma unroll
            for (int i = 0; i < G1_TM; i++)
                av[i] = *(const float4*)(As + (lane + 32 * i) * G1_ASTR + k0);

            #pragma unroll
            for (int kk = 0; kk < 4; kk++) {
                const float* brow = Bs + (k0 + kk) * HID + c0;   // broadcast
                float4 q0 = *(const float4*)brow;
                float4 q1 = *(const float4*)(brow + 4);
                ull bf[4] = { pack2(q0.x, q0.y), pack2(q0.z, q0.w),
                              pack2(q1.x, q1.y), pack2(q1.z, q1.w) };
                #pragma unroll
                for (int i = 0; i < G1_TM; i++) {
                    float a = (kk == 0) ? av[i].x : (kk == 1) ? av[i].y
                            : (kk == 2) ? av[i].z : av[i].w;
                    ull a2 = pack2(a, a);
                    #pragma unroll
                    for (int j = 0; j < 4; j++)
                        acc[i][j] = fma2(a2, bf[j], acc[i][j]);
                }
            }
        }

        #pragma unroll
        for (int i = 0; i < G1_TM; i++) {
            int row = row0 + lane + 32 * i;
            float* op = g_cur + (size_t)row * HID + c0;
            float l0, h0, l1, h1, l2, h2, l3, h3;
            unpack2(acc[i][0], l0, h0); unpack2(acc[i][1], l1, h1);
            unpack2(acc[i][2], l2, h2); unpack2(acc[i][3], l3, h3);
            *(float4*)op       = make_float4(l0, h0, l1, h1);
            *(float4*)(op + 4) = make_float4(l2, h2, l3, h3);
        }
    }
}

// ================= LIF kernels ==============================================
// 14 groups of 64 threads (2 warps) per CTA -> 148*14=2072 >= 2048: ONE pass.
// Thread i (i<50) handles neurons 4i..4i+3 (LDS.128 + 2x add.f32x2 per spike).
// Mask format: 8 words/t; word m = 4*wig + q covers neurons 128*wig + 4*lane + q.
#define L_GROUPS 14
#define GW 64
#define L_THREADS (L_GROUPS * GW)               // 896
#define W_SMEM (HID * HID * 4)                  // 160000 B

__device__ __forceinline__ void group_bar(int grp) {
    asm volatile("bar.sync %0, %1;" :: "r"(grp + 1), "r"(GW) : "memory");
}

// Warp-uniform sparse scan: acc over spiking rows h; 4 cols per thread.
__device__ __forceinline__ void scan4(const unsigned* words, const float4* Ws4,
                                      int i, ull& accA, ull& accB) {
    #pragma unroll
    for (int m = 0; m < 8; m++) {
        unsigned u = words[m];
        const int base = ((m >> 2) << 7) + (m & 3);
        while (u) {                                   // uniform among active lanes
            int j = __ffs(u) - 1;
            u &= u - 1;
            int h = base + (j << 2);
            float4 wv = Ws4[h * 50 + i];
            accA = add2(accA, pack2(wv.x, wv.y));
            accB = add2(accB, pack2(wv.z, wv.w));
        }
    }
}

// ------- Kernel 2: LIF1 + sparse GEMM2 + LIF2 -> spk2 masks -------
__global__ __launch_bounds__(L_THREADS, 1)
void lif2_kernel(const float* __restrict__ W2, const float* __restrict__ b2) {
    extern __shared__ float smem[];
    const float4* Ws4 = (const float4*)smem;           // [200][50] float4
    __shared__ unsigned sw[2][L_GROUPS][8];
    const int tid = threadIdx.x;
    for (int k = tid; k < HID * HID; k += L_THREADS) smem[k] = W2[k];

    const int  grp  = tid / GW;
    const int  i    = tid - grp * GW;      // 0..63
    const int  lane = i & 31;
    const int  wig  = i >> 5;              // warp in group (0,1)
    const bool iv   = (i < 50);            // active: neurons 4i..4i+3
    float4 bias = make_float4(0.f, 0.f, 0.f, 0.f);
    if (iv) bias = *(const float4*)(b2 + 4 * i);
    __syncthreads();

    for (int b = blockIdx.x * L_GROUPS + grp; b < BATCH; b += gridDim.x * L_GROUPS) {
        float v10 = 0.f, v11 = 0.f, v12 = 0.f, v13 = 0.f;
        float v20 = 0.f, v21 = 0.f, v22 = 0.f, v23 = 0.f;
        const float4* curp = (const float4*)(g_cur + (size_t)b * S_LEN * HID) + (iv ? i : 0);
        unsigned*     spk  = g_spk2 + (size_t)b * S_LEN * 8;

        const int P = 4;
        float4 buf[P];
        #pragma unroll
        for (int q = 0; q < P; q++) buf[q] = iv ? curp[q * 50] : make_float4(0,0,0,0);

        for (int t = 0; t < S_LEN; t++) {
            float4 cur = buf[t & (P - 1)];
            int tp = t + P; if (tp > S_LEN - 1) tp = S_LEN - 1;
            if (iv) buf[t & (P - 1)] = curp[tp * 50];   // prefetch (indep of v)

            v10 = 0.5f * (v10 + cur.x); v11 = 0.5f * (v11 + cur.y);
            v12 = 0.5f * (v12 + cur.z); v13 = 0.5f * (v13 + cur.w);
            bool s0 = iv && (v10 >= 1.0f); if (s0) v10 = 0.f;
            bool s1 = iv && (v11 >= 1.0f); if (s1) v11 = 0.f;
            bool s2 = iv && (v12 >= 1.0f); if (s2) v12 = 0.f;
            bool s3 = iv && (v13 >= 1.0f); if (s3) v13 = 0.f;
            unsigned m0 = __ballot_sync(0xffffffffu, s0);
            unsigned m1 = __ballot_sync(0xffffffffu, s1);
            unsigned m2 = __ballot_sync(0xffffffffu, s2);
            unsigned m3 = __ballot_sync(0xffffffffu, s3);
            if (lane == 0) {
                unsigned* swp = sw[t & 1][grp] + 4 * wig;
                swp[0] = m0; swp[1] = m1; swp[2] = m2; swp[3] = m3;
            }
            group_bar(grp);

            ull accA = pack2(bias.x, bias.y), accB = pack2(bias.z, bias.w);
            if (iv) scan4(sw[t & 1][grp], Ws4, i, accA, accB);
            float a0, a1, a2, a3;
            unpack2(accA, a0, a1); unpack2(accB, a2, a3);

            v20 = 0.5f * (v20 + a0); v21 = 0.5f * (v21 + a1);
            v22 = 0.5f * (v22 + a2); v23 = 0.5f * (v23 + a3);
            bool r0 = iv && (v20 >= 1.0f); if (r0) v20 = 0.f;
            bool r1 = iv && (v21 >= 1.0f); if (r1) v21 = 0.f;
            bool r2 = iv && (v22 >= 1.0f); if (r2) v22 = 0.f;
            bool r3 = iv && (v23 >= 1.0f); if (r3) v23 = 0.f;
            unsigned n0 = __ballot_sync(0xffffffffu, r0);
            unsigned n1 = __ballot_sync(0xffffffffu, r1);
            unsigned n2 = __ballot_sync(0xffffffffu, r2);
            unsigned n3 = __ballot_sync(0xffffffffu, r3);
            if (lane == 0) {
                unsigned* sp = spk + (size_t)t * 8 + 4 * wig;
                sp[0] = n0; sp[1] = n1; sp[2] = n2; sp[3] = n3;
            }
        }
    }
}

// ------- Kernel 3: sparse GEMM3 + LIF3 + fused readout/log_softmax -------
__global__ __launch_bounds__(L_THREADS, 1)
void lif3_kernel(const float* __restrict__ W3, const float* __restrict__ b3,
                 const float* __restrict__ Wr, const float* __restrict__ br,
                 float* __restrict__ out) {
    extern __shared__ float smem[];
    const float4* Ws4 = (const float4*)smem;
    __shared__ float cnt_sm[L_GROUPS][HID];
    const int tid = threadIdx.x;
    for (int k = tid; k < HID * HID; k += L_THREADS) smem[k] = W3[k];

    const int  grp  = tid / GW;
    const int  i    = tid - grp * GW;
    const int  lane = i & 31;
    const int  wig  = i >> 5;
    const bool iv   = (i < 50);
    float4 bias = make_float4(0.f, 0.f, 0.f, 0.f);
    if (iv) bias = *(const float4*)(b3 + 4 * i);
    __syncthreads();

    for (int b = blockIdx.x * L_GROUPS + grp; b < BATCH; b += gridDim.x * L_GROUPS) {
        float v30 = 0.f, v31 = 0.f, v32 = 0.f, v33 = 0.f;
        int c0 = 0, c1 = 0, c2 = 0, c3 = 0;
        const unsigned* sp = g_spk2 + (size_t)b * S_LEN * 8;

        unsigned curm[8];
        #pragma unroll
        for (int w = 0; w < 8; w++) curm[w] = __ldg(sp + w);

        for (int t = 0; t < S_LEN; t++) {
            unsigned nxtm[8];
            const unsigned* spn = sp + (size_t)((t + 1 < S_LEN) ? t + 1 : t) * 8;
            #pragma unroll
            for (int w = 0; w < 8; w++) nxtm[w] = __ldg(spn + w);   // prefetch

            ull accA = pack2(bias.x, bias.y), accB = pack2(bias.z, bias.w);
            if (iv) scan4(curm, Ws4, i, accA, accB);
            float a0, a1, a2, a3;
            unpack2(accA, a0, a1); unpack2(accB, a2, a3);

            v30 = 0.5f * (v30 + a0); if (v30 >= 1.0f) { v30 = 0.f; c0++; }
            v31 = 0.5f * (v31 + a1); if (v31 >= 1.0f) { v31 = 0.f; c1++; }
            v32 = 0.5f * (v32 + a2); if (v32 >= 1.0f) { v32 = 0.f; c2++; }
            v33 = 0.5f * (v33 + a3); if (v33 >= 1.0f) { v33 = 0.f; c3++; }
            #pragma unroll
            for (int w = 0; w < 8; w++) curm[w] = nxtm[w];
        }
        if (iv)
            *(float4*)&cnt_sm[grp][4 * i] =
                make_float4((float)c0, (float)c1, (float)c2, (float)c3);
        group_bar(grp);

        if (wig == 0) {                    // warp 0 of group: readout for this b
            float o = -3.0e38f;
            if (lane < DOUT) {
                float acc = 0.f;
                #pragma unroll 4
                for (int k = 0; k < HID; k++)
                    acc += cnt_sm[grp][k] * Wr[k * DOUT + lane];
                o = acc * (1.0f / 101.0f) + br[lane];
            }
            float m = o;
            #pragma unroll
            for (int off = 16; off; off >>= 1)
                m = fmaxf(m, __shfl_xor_sync(0xffffffffu, m, off));
            float e = (lane < DOUT) ? expf(o - m) : 0.f;
            float ssum = e;
            #pragma unroll
            for (int off = 16; off; off >>= 1)
                ssum += __shfl_xor_sync(0xffffffffu, ssum, off);
            if (lane < DOUT) out[b * DOUT + lane] = (o - m) - logf(ssum);
        }
        group_bar(grp);                    // protect cnt_sm before next b iter
    }
}

// ================= launch ====================================================
extern "C" void kernel_launch(void* const* d_in, const int* in_sizes, int n_in,
                              void* d_out, int out_size) {
    const float* x  = (const float*)d_in[0];
    const float* W1 = (const float*)d_in[1];
    const float* b1 = (const float*)d_in[2];
    const float* W2 = (const float*)d_in[3];
    const float* b2 = (const float*)d_in[4];
    const float* W3 = (const float*)d_in[5];
    const float* b3 = (const float*)d_in[6];
    const float* Wr = (const float*)d_in[7];
    const float* br = (const float*)d_in[8];
    float* out = (float*)d_out;

    cudaFuncSetAttribute(gemm1_kernel, cudaFuncAttributeMaxDynamicSharedMemorySize, G1_SMEM);
    cudaFuncSetAttribute(lif2_kernel,  cudaFuncAttributeMaxDynamicSharedMemorySize, W_SMEM);
    cudaFuncSetAttribute(lif3_kernel,  cudaFuncAttributeMaxDynamicSharedMemorySize, W_SMEM);

    const int grid = 148;   // 1 CTA/SM (smem-bound); persistent stride loops

    gemm1_kernel<<<grid, G1_THREADS, G1_SMEM>>>(x, W1, b1);
    lif2_kernel <<<grid, L_THREADS,  W_SMEM>>>(W2, b2);
    lif3_kernel <<<grid, L_THREADS,  W_SMEM>>>(W3, b3, Wr, br, out);
}

// round 6
// speedup vs baseline: 1.8988x; 1.0686x over previous
#include <cuda_runtime.h>
#include <cstdint>

#define S_LEN 101
#define BATCH 2048
#define HID 200
#define DIN 120
#define DOUT 12
#define M_TOTAL (S_LEN * BATCH)   // 206848

// Scratch (no allocations allowed -> __device__ globals)
// b-major layouts: cur[b][t][n], spk2[b][t][w] (8 mask words per t)
__device__ float    g_cur[(size_t)M_TOTAL * HID];     // ~165 MB
__device__ unsigned g_spk2[(size_t)M_TOTAL * 8];      // ~6.6 MB

typedef unsigned long long ull;

// ---------- packed f32x2 helpers ----------
__device__ __forceinline__ ull pack2(float lo, float hi) {
    ull r;
    asm("mov.b64 %0, {%1,%2};" : "=l"(r) : "f"(lo), "f"(hi));
    return r;
}
__device__ __forceinline__ void unpack2(ull v, float& lo, float& hi) {
    asm("mov.b64 {%0,%1}, %2;" : "=f"(lo), "=f"(hi) : "l"(v));
}
__device__ __forceinline__ ull fma2(ull a, ull b, ull c) {
    ull d;
    asm("fma.rn.f32x2 %0, %1, %2, %3;" : "=l"(d) : "l"(a), "l"(b), "l"(c));
    return d;
}
__device__ __forceinline__ ull add2(ull a, ull b) {
    ull d;
    asm("add.rn.f32x2 %0, %1, %2;" : "=l"(d) : "l"(a), "l"(b));
    return d;
}
__device__ __forceinline__ void ldgsts16(unsigned saddr, const void* gptr) {
    asm volatile("cp.async.cg.shared.global [%0], [%1], 16;"
                 :: "r"(saddr), "l"(gptr));
}
__device__ __forceinline__ void cpa_commit() {
    asm volatile("cp.async.commit_group;" ::: "memory");
}
__device__ __forceinline__ void cpa_wait1() {
    asm volatile("cp.async.wait_group 1;" ::: "memory");
}

// ================= Kernel 1: CUR1 = X @ W1 + b1 =================
// Double-buffered As via cp.async; compute mapping unchanged from R4/R5.
// 800 threads = 25 warps; warp -> 8 cols (broadcast B), lane -> rows lane+32i.
#define G1_BM 128
#define G1_TM 4
#define G1_THREADS 800
#define G1_ASTR 124
#define G1_ABUF (G1_BM * G1_ASTR)                       // floats per As buffer
#define G1_CHUNKS (G1_BM * 30)                          // 16B chunks per tile
#define G1_SMEM ((2 * G1_ABUF + DIN * HID) * 4)         // 222976 B

__global__ __launch_bounds__(G1_THREADS, 1)
void gemm1_kernel(const float* __restrict__ x,
                  const float* __restrict__ W1,
                  const float* __restrict__ b1) {
    extern __shared__ float smem[];
    float* As0 = smem;                       // [128][124]
    float* As1 = smem + G1_ABUF;             // [128][124]
    float* Bs  = smem + 2 * G1_ABUF;         // [120][200]
    const int tid  = threadIdx.x;
    const int warp = tid >> 5;
    const int lane = tid & 31;
    const int c0   = warp * 8;
    const int ntiles = M_TOTAL / G1_BM;      // 1616 exact

    const unsigned sA0 = (unsigned)__cvta_generic_to_shared(As0);
    const unsigned sA1 = (unsigned)__cvta_generic_to_shared(As1);

    // issue cp.async loads for one tile into one As buffer (x transpose-gather)
    auto issue_tile = [&](int tile, unsigned sbase) {
        if (tile < ntiles) {
            const int row0 = tile * G1_BM;
            for (int i = tid; i < G1_CHUNKS; i += G1_THREADS) {
                int r  = i / 30;
                int cs = i - r * 30;
                int c  = cs / 10;            // channel 0..2
                int j  = cs - c * 10;        // 16B chunk within channel
                int row = row0 + r;
                int b = row / S_LEN, t = row - b * S_LEN;
                const float* gp = x + ((size_t)((b * 3 + c) * S_LEN + t)) * 40 + j * 4;
                unsigned sp = sbase + (unsigned)(r * G1_ASTR + c * 40 + j * 4) * 4u;
                ldgsts16(sp, gp);
            }
        }
        cpa_commit();
    };

    // start first tile's loads ASAP, then fill Bs
    int tile = blockIdx.x;
    issue_tile(tile, sA0);                                  // group 0
    for (int i = tid; i < DIN * HID; i += G1_THREADS) Bs[i] = W1[i];

    ull bj[4];
    {
        float4 q0 = *(const float4*)(b1 + c0);
        float4 q1 = *(const float4*)(b1 + c0 + 4);
        bj[0] = pack2(q0.x, q0.y); bj[1] = pack2(q0.z, q0.w);
        bj[2] = pack2(q1.x, q1.y); bj[3] = pack2(q1.z, q1.w);
    }

    int idx = 0;
    for (; tile < ntiles; tile += gridDim.x, idx ^= 1) {
        issue_tile(tile + gridDim.x, idx ? sA0 : sA1);      // prefetch next
        cpa_wait1();                                        // current tile ready
        __syncthreads();

        const float* As = idx ? As1 : As0;
        ull acc[G1_TM][4];
        #pragma unroll
        for (int i = 0; i < G1_TM; i++)
            #pragma unroll
            for (int j = 0; j < 4; j++) acc[i][j] = bj[j];

        for (int k0 = 0; k0 < DIN; k0 += 4) {
            float4 av[G1_TM];
            #pragma unroll
            for (int i = 0; i < G1_TM; i++)
                av[i] = *(const float4*)(As + (lane + 32 * i) * G1_ASTR + k0);

            #pragma unroll
            for (int kk = 0; kk < 4; kk++) {
                const float* brow = Bs + (k0 + kk) * HID + c0;   // broadcast
                float4 q0 = *(const float4*)brow;
                float4 q1 = *(const float4*)(brow + 4);
                ull bf[4] = { pack2(q0.x, q0.y), pack2(q0.z, q0.w),
                              pack2(q1.x, q1.y), pack2(q1.z, q1.w) };
                #pragma unroll
                for (int i = 0; i < G1_TM; i++) {
                    float a = (kk == 0) ? av[i].x : (kk == 1) ? av[i].y
                            : (kk == 2) ? av[i].z : av[i].w;
                    ull a2 = pack2(a, a);
                    #pragma unroll
                    for (int j = 0; j < 4; j++)
                        acc[i][j] = fma2(a2, bf[j], acc[i][j]);
                }
            }
        }

        const int row0 = tile * G1_BM;
        #pragma unroll
        for (int i = 0; i < G1_TM; i++) {
            int row = row0 + lane + 32 * i;
            float* op = g_cur + (size_t)row * HID + c0;
            float l0, h0, l1, h1, l2, h2, l3, h3;
            unpack2(acc[i][0], l0, h0); unpack2(acc[i][1], l1, h1);
            unpack2(acc[i][2], l2, h2); unpack2(acc[i][3], l3, h3);
            *(float4*)op       = make_float4(l0, h0, l1, h1);
            *(float4*)(op + 4) = make_float4(l2, h2, l3, h3);
        }
        __syncthreads();   // next iter's cp.async overwrites this buffer
    }
}

// ================= LIF kernels (unchanged from R5, ~151us total) =============
// 14 groups of 64 threads (2 warps) per CTA -> 148*14=2072 >= 2048: ONE pass.
// Thread i (i<50) handles neurons 4i..4i+3 (LDS.128 + 2x add.f32x2 per spike).
#define L_GROUPS 14
#define GW 64
#define L_THREADS (L_GROUPS * GW)               // 896
#define W_SMEM (HID * HID * 4)                  // 160000 B

__device__ __forceinline__ void group_bar(int grp) {
    asm volatile("bar.sync %0, %1;" :: "r"(grp + 1), "r"(GW) : "memory");
}

__device__ __forceinline__ void scan4(const unsigned* words, const float4* Ws4,
                                      int i, ull& accA, ull& accB) {
    #pragma unroll
    for (int m = 0; m < 8; m++) {
        unsigned u = words[m];
        const int base = ((m >> 2) << 7) + (m & 3);
        while (u) {                                   // uniform among active lanes
            int j = __ffs(u) - 1;
            u &= u - 1;
            int h = base + (j << 2);
            float4 wv = Ws4[h * 50 + i];
            accA = add2(accA, pack2(wv.x, wv.y));
            accB = add2(accB, pack2(wv.z, wv.w));
        }
    }
}

__global__ __launch_bounds__(L_THREADS, 1)
void lif2_kernel(const float* __restrict__ W2, const float* __restrict__ b2) {
    extern __shared__ float smem[];
    const float4* Ws4 = (const float4*)smem;           // [200][50] float4
    __shared__ unsigned sw[2][L_GROUPS][8];
    const int tid = threadIdx.x;
    for (int k = tid; k < HID * HID; k += L_THREADS) smem[k] = W2[k];

    const int  grp  = tid / GW;
    const int  i    = tid - grp * GW;      // 0..63
    const int  lane = i & 31;
    const int  wig  = i >> 5;              // warp in group (0,1)
    const bool iv   = (i < 50);            // active: neurons 4i..4i+3
    float4 bias = make_float4(0.f, 0.f, 0.f, 0.f);
    if (iv) bias = *(const float4*)(b2 + 4 * i);
    __syncthreads();

    for (int b = blockIdx.x * L_GROUPS + grp; b < BATCH; b += gridDim.x * L_GROUPS) {
        float v10 = 0.f, v11 = 0.f, v12 = 0.f, v13 = 0.f;
        float v20 = 0.f, v21 = 0.f, v22 = 0.f, v23 = 0.f;
        const float4* curp = (const float4*)(g_cur + (size_t)b * S_LEN * HID) + (iv ? i : 0);
        unsigned*     spk  = g_spk2 + (size_t)b * S_LEN * 8;

        const int P = 4;
        float4 buf[P];
        #pragma unroll
        for (int q = 0; q < P; q++) buf[q] = iv ? curp[q * 50] : make_float4(0,0,0,0);

        for (int t = 0; t < S_LEN; t++) {
            float4 cur = buf[t & (P - 1)];
            int tp = t + P; if (tp > S_LEN - 1) tp = S_LEN - 1;
            if (iv) buf[t & (P - 1)] = curp[tp * 50];   // prefetch (indep of v)

            v10 = 0.5f * (v10 + cur.x); v11 = 0.5f * (v11 + cur.y);
            v12 = 0.5f * (v12 + cur.z); v13 = 0.5f * (v13 + cur.w);
            bool s0 = iv && (v10 >= 1.0f); if (s0) v10 = 0.f;
            bool s1 = iv && (v11 >= 1.0f); if (s1) v11 = 0.f;
            bool s2 = iv && (v12 >= 1.0f); if (s2) v12 = 0.f;
            bool s3 = iv && (v13 >= 1.0f); if (s3) v13 = 0.f;
            unsigned m0 = __ballot_sync(0xffffffffu, s0);
            unsigned m1 = __ballot_sync(0xffffffffu, s1);
            unsigned m2 = __ballot_sync(0xffffffffu, s2);
            unsigned m3 = __ballot_sync(0xffffffffu, s3);
            if (lane == 0) {
                unsigned* swp = sw[t & 1][grp] + 4 * wig;
                swp[0] = m0; swp[1] = m1; swp[2] = m2; swp[3] = m3;
            }
            group_bar(grp);

            ull accA = pack2(bias.x, bias.y), accB = pack2(bias.z, bias.w);
            if (iv) scan4(sw[t & 1][grp], Ws4, i, accA, accB);
            float a0, a1, a2, a3;
            unpack2(accA, a0, a1); unpack2(accB, a2, a3);

            v20 = 0.5f * (v20 + a0); v21 = 0.5f * (v21 + a1);
            v22 = 0.5f * (v22 + a2); v23 = 0.5f * (v23 + a3);
            bool r0 = iv && (v20 >= 1.0f); if (r0) v20 = 0.f;
            bool r1 = iv && (v21 >= 1.0f); if (r1) v21 = 0.f;
            bool r2 = iv && (v22 >= 1.0f); if (r2) v22 = 0.f;
            bool r3 = iv && (v23 >= 1.0f); if (r3) v23 = 0.f;
            unsigned n0 = __ballot_sync(0xffffffffu, r0);
            unsigned n1 = __ballot_sync(0xffffffffu, r1);
            unsigned n2 = __ballot_sync(0xffffffffu, r2);
            unsigned n3 = __ballot_sync(0xffffffffu, r3);
            if (lane == 0) {
                unsigned* sp = spk + (size_t)t * 8 + 4 * wig;
                sp[0] = n0; sp[1] = n1; sp[2] = n2; sp[3] = n3;
            }
        }
    }
}

__global__ __launch_bounds__(L_THREADS, 1)
void lif3_kernel(const float* __restrict__ W3, const float* __restrict__ b3,
                 const float* __restrict__ Wr, const float* __restrict__ br,
                 float* __restrict__ out) {
    extern __shared__ float smem[];
    const float4* Ws4 = (const float4*)smem;
    __shared__ float cnt_sm[L_GROUPS][HID];
    const int tid = threadIdx.x;
    for (int k = tid; k < HID * HID; k += L_THREADS) smem[k] = W3[k];

    const int  grp  = tid / GW;
    const int  i    = tid - grp * GW;
    const int  lane = i & 31;
    const int  wig  = i >> 5;
    const bool iv   = (i < 50);
    float4 bias = make_float4(0.f, 0.f, 0.f, 0.f);
    if (iv) bias = *(const float4*)(b3 + 4 * i);
    __syncthreads();

    for (int b = blockIdx.x * L_GROUPS + grp; b < BATCH; b += gridDim.x * L_GROUPS) {
        float v30 = 0.f, v31 = 0.f, v32 = 0.f, v33 = 0.f;
        int c0 = 0, c1 = 0, c2 = 0, c3 = 0;
        const unsigned* sp = g_spk2 + (size_t)b * S_LEN * 8;

        unsigned curm[8];
        #pragma unroll
        for (int w = 0; w < 8; w++) curm[w] = __ldg(sp + w);

        for (int t = 0; t < S_LEN; t++) {
            unsigned nxtm[8];
            const unsigned* spn = sp + (size_t)((t + 1 < S_LEN) ? t + 1 : t) * 8;
            #pragma unroll
            for (int w = 0; w < 8; w++) nxtm[w] = __ldg(spn + w);   // prefetch

            ull accA = pack2(bias.x, bias.y), accB = pack2(bias.z, bias.w);
            if (iv) scan4(curm, Ws4, i, accA, accB);
            float a0, a1, a2, a3;
            unpack2(accA, a0, a1); unpack2(accB, a2, a3);

            v30 = 0.5f * (v30 + a0); if (v30 >= 1.0f) { v30 = 0.f; c0++; }
            v31 = 0.5f * (v31 + a1); if (v31 >= 1.0f) { v31 = 0.f; c1++; }
            v32 = 0.5f * (v32 + a2); if (v32 >= 1.0f) { v32 = 0.f; c2++; }
            v33 = 0.5f * (v33 + a3); if (v33 >= 1.0f) { v33 = 0.f; c3++; }
            #pragma unroll
            for (int w = 0; w < 8; w++) curm[w] = nxtm[w];
        }
        if (iv)
            *(float4*)&cnt_sm[grp][4 * i] =
                make_float4((float)c0, (float)c1, (float)c2, (float)c3);
        group_bar(grp);

        if (wig == 0) {                    // warp 0 of group: readout for this b
            float o = -3.0e38f;
            if (lane < DOUT) {
                float acc = 0.f;
                #pragma unroll 4
                for (int k = 0; k < HID; k++)
                    acc += cnt_sm[grp][k] * Wr[k * DOUT + lane];
                o = acc * (1.0f / 101.0f) + br[lane];
            }
            float m = o;
            #pragma unroll
            for (int off = 16; off; off >>= 1)
                m = fmaxf(m, __shfl_xor_sync(0xffffffffu, m, off));
            float e = (lane < DOUT) ? expf(o - m) : 0.f;
            float ssum = e;
            #pragma unroll
            for (int off = 16; off; off >>= 1)
                ssum += __shfl_xor_sync(0xffffffffu, ssum, off);
            if (lane < DOUT) out[b * DOUT + lane] = (o - m) - logf(ssum);
        }
        group_bar(grp);                    // protect cnt_sm before next b iter
    }
}

// ================= launch ====================================================
extern "C" void kernel_launch(void* const* d_in, const int* in_sizes, int n_in,
                              void* d_out, int out_size) {
    const float* x  = (const float*)d_in[0];
    const float* W1 = (const float*)d_in[1];
    const float* b1 = (const float*)d_in[2];
    const float* W2 = (const float*)d_in[3];
    const float* b2 = (const float*)d_in[4];
    const float* W3 = (const float*)d_in[5];
    const float* b3 = (const float*)d_in[6];
    const float* Wr = (const float*)d_in[7];
    const float* br = (const float*)d_in[8];
    float* out = (float*)d_out;

    cudaFuncSetAttribute(gemm1_kernel, cudaFuncAttributeMaxDynamicSharedMemorySize, G1_SMEM);
    cudaFuncSetAttribute(lif2_kernel,  cudaFuncAttributeMaxDynamicSharedMemorySize, W_SMEM);
    cudaFuncSetAttribute(lif3_kernel,  cudaFuncAttributeMaxDynamicSharedMemorySize, W_SMEM);

    const int grid = 148;   // 1 CTA/SM (smem-bound); persistent stride loops

    gemm1_kernel<<<grid, G1_THREADS, G1_SMEM>>>(x, W1, b1);
    lif2_kernel <<<grid, L_THREADS,  W_SMEM>>>(W2, b2);
    lif3_kernel <<<grid, L_THREADS,  W_SMEM>>>(W3, b3, Wr, br, out);
}

// round 8
// speedup vs baseline: 2.4787x; 1.3054x over previous
#include <cuda_runtime.h>
#include <cstdint>

#define S_LEN 101
#define BATCH 2048
#define HID 200
#define DIN 120
#define DOUT 12
#define M_TOTAL (S_LEN * BATCH)   // 206848

// Scratch (no allocations allowed -> __device__ globals)
__device__ float    g_cur[(size_t)M_TOTAL * HID];     // ~165 MB  cur[b][t][n]
__device__ unsigned g_spk2[(size_t)M_TOTAL * 8];      // ~6.6 MB  spk2[b][t][w]

typedef unsigned long long ull;

// ---------- packed f32x2 helpers (lif kernels) ----------
__device__ __forceinline__ ull pack2(float lo, float hi) {
    ull r; asm("mov.b64 %0, {%1,%2};" : "=l"(r) : "f"(lo), "f"(hi)); return r;
}
__device__ __forceinline__ void unpack2(ull v, float& lo, float& hi) {
    asm("mov.b64 {%0,%1}, %2;" : "=f"(lo), "=f"(hi) : "l"(v));
}
__device__ __forceinline__ ull add2(ull a, ull b) {
    ull d; asm("add.rn.f32x2 %0, %1, %2;" : "=l"(d) : "l"(a), "l"(b)); return d;
}

// ---------- mma / cp.async helpers ----------
__device__ __forceinline__ unsigned tf32of(float x) {
    unsigned u; asm("cvt.rna.tf32.f32 %0, %1;" : "=r"(u) : "f"(x)); return u;
}
__device__ __forceinline__ void mma_tf32(float* c,
                                         unsigned a0, unsigned a1, unsigned a2, unsigned a3,
                                         unsigned b0, unsigned b1) {
    asm volatile(
        "mma.sync.aligned.m16n8k8.row.col.f32.tf32.tf32.f32 "
        "{%0,%1,%2,%3}, {%4,%5,%6,%7}, {%8,%9}, {%0,%1,%2,%3};"
        : "+f"(c[0]), "+f"(c[1]), "+f"(c[2]), "+f"(c[3])
        : "r"(a0), "r"(a1), "r"(a2), "r"(a3), "r"(b0), "r"(b1));
}
__device__ __forceinline__ void ldgsts16(unsigned saddr, const void* gptr) {
    asm volatile("cp.async.cg.shared.global [%0], [%1], 16;" :: "r"(saddr), "l"(gptr));
}
#define CPA_COMMIT() asm volatile("cp.async.commit_group;" ::: "memory")
#define CPA_WAIT1()  asm volatile("cp.async.wait_group 1;" ::: "memory")

// ================= Kernel 1: CUR1 = X @ W1 + b1 via mma.sync TF32 3x-split ===
// Even CTAs: cols 0..103 (13 n-frags); odd CTAs: cols 104..199 (12 n-frags).
// B (W1 half) pre-split hi/lo into fragment-native smem (one LDS.128/frag).
// A staged fp32 via cp.async (double buffer), converted per-fragment on the fly.
#define GM_THREADS 256
#define NFMAX 13
#define GM_STR 124
#define GM_STG (128 * GM_STR)                          // floats per stage buffer
#define BF_BYTES (15 * NFMAX * 32 * 16)                // 99840
#define GM_SMEM (BF_BYTES + 2 * GM_STG * 4)            // 226816 B
#define MTILES (M_TOTAL / 128)                         // 1616

__global__ __launch_bounds__(GM_THREADS, 1)
void gemm1_mma_kernel(const float* __restrict__ x,
                      const float* __restrict__ W1,
                      const float* __restrict__ b1) {
    extern __shared__ char sm[];
    float4* Bf  = (float4*)sm;                         // [15][13][32]
    float*  As0 = (float*)(sm + BF_BYTES);             // [128][124]
    float*  As1 = As0 + GM_STG;

    const int tid   = threadIdx.x;
    const int warp  = tid >> 5;
    const int lane  = tid & 31;
    const int group = lane >> 2;       // tid/4  (0..7)
    const int tg    = lane & 3;        // tid%4  (0..3)
    const int half  = blockIdx.x & 1;
    const int colbase = half ? 104 : 0;
    const int nfc     = half ? 12 : 13;                // n-fragments (8 cols each)

    const unsigned sA0 = (unsigned)__cvta_generic_to_shared(As0);
    const unsigned sA1 = (unsigned)__cvta_generic_to_shared(As1);

    // issue cp.async loads for one tile into one stage buffer (x gather)
    auto issue_stage = [&](int mt, unsigned sbase) {
        if (mt < MTILES) {
            const int row0 = mt * 128;
            for (int i = tid; i < 128 * 30; i += GM_THREADS) {
                int r = i / 30, cs = i - r * 30;
                int c = cs / 10, j = cs - c * 10;
                int row = row0 + r;
                int b = row / S_LEN, t = row - b * S_LEN;
                const float* gp = x + ((size_t)((b * 3 + c) * S_LEN + t)) * 40 + j * 4;
                unsigned sp = sbase + (unsigned)((r * GM_STR + c * 40 + j * 4) * 4);
                ldgsts16(sp, gp);
            }
        }
        CPA_COMMIT();
    };

    int m = blockIdx.x >> 1;
    issue_stage(m, sA0);               // group 0 in flight while we build Bf

    // ---- pre-split B = W1 half into fragment-native hi/lo layout ----
    // Bf[ks][nf][t] = {b0hi, b1hi, b0lo, b1lo};  b0 = W1[8ks+tg][n], b1 = +4 k
    for (int idx = tid; idx < 15 * nfc * 32; idx += GM_THREADS) {
        int ks  = idx / (nfc * 32);
        int rem = idx - ks * nfc * 32;
        int nf  = rem >> 5;
        int t   = rem & 31;
        int g = t >> 2, q = t & 3;
        int k = ks * 8 + q;
        int n = colbase + nf * 8 + g;
        float w0 = W1[k * HID + n];
        float w1 = W1[(k + 4) * HID + n];
        unsigned h0 = tf32of(w0), h1 = tf32of(w1);
        unsigned l0 = tf32of(w0 - __uint_as_float(h0));
        unsigned l1 = tf32of(w1 - __uint_as_float(h1));
        Bf[(ks * NFMAX + nf) * 32 + t] =
            make_float4(__uint_as_float(h0), __uint_as_float(h1),
                        __uint_as_float(l0), __uint_as_float(l1));
    }

    // bias per accumulator column pair: col = colbase + nf*8 + 2*tg (+1)
    float2 bias[NFMAX];
    #pragma unroll
    for (int nf = 0; nf < NFMAX; nf++) {
        if (nf < nfc) {
            int c = colbase + nf * 8 + 2 * tg;
            bias[nf] = make_float2(b1[c], b1[c + 1]);
        } else bias[nf] = make_float2(0.f, 0.f);
    }

    int idx = 0;
    for (; m < MTILES; m += 74, idx ^= 1) {
        issue_stage(m + 74, idx ? sA0 : sA1);          // prefetch next
        CPA_WAIT1();                                   // current stage ready
        __syncthreads();                               // + Bf visible (1st iter)

        const float* As = idx ? As1 : As0;
        const float* arow = As + (warp * 16 + group) * GM_STR;

        float acc[NFMAX][4];
        #pragma unroll
        for (int nf = 0; nf < NFMAX; nf++) {
            acc[nf][0] = bias[nf].x; acc[nf][1] = bias[nf].y;
            acc[nf][2] = bias[nf].x; acc[nf][3] = bias[nf].y;
        }

        #pragma unroll
        for (int ks = 0; ks < 15; ks++) {
            const int k0 = ks * 8;
            float a0 = arow[k0 + tg];
            float a2 = arow[k0 + tg + 4];
            float a1 = arow[8 * GM_STR + k0 + tg];
            float a3 = arow[8 * GM_STR + k0 + tg + 4];
            unsigned ah0 = tf32of(a0), ah1 = tf32of(a1),
                     ah2 = tf32of(a2), ah3 = tf32of(a3);
            unsigned al0 = tf32of(a0 - __uint_as_float(ah0));
            unsigned al1 = tf32of(a1 - __uint_as_float(ah1));
            unsigned al2 = tf32of(a2 - __uint_as_float(ah2));
            unsigned al3 = tf32of(a3 - __uint_as_float(ah3));

            const float4* bp = Bf + ks * NFMAX * 32 + lane;
            #pragma unroll
            for (int nf = 0; nf < NFMAX; nf++) {
                if (nf < nfc) {
                    float4 b = bp[nf * 32];                       // LDS.128
                    unsigned bh0 = __float_as_uint(b.x), bh1 = __float_as_uint(b.y);
                    unsigned bl0 = __float_as_uint(b.z), bl1 = __float_as_uint(b.w);
                    mma_tf32(acc[nf], ah0, ah1, ah2, ah3, bh0, bh1);   // hi*hi
                    mma_tf32(acc[nf], ah0, ah1, ah2, ah3, bl0, bl1);   // hi*lo
                    mma_tf32(acc[nf], al0, al1, al2, al3, bh0, bh1);   // lo*hi
                }
            }
        }

        // epilogue: c0/c1 at (row=16w+group, col=nf*8+2tg), c2/c3 at row+8
        const int r0 = m * 128 + warp * 16 + group;
        float* op = g_cur + (size_t)r0 * HID + colbase;
        #pragma unroll
        for (int nf = 0; nf < NFMAX; nf++) {
            if (nf < nfc) {
                *(float2*)(op + nf * 8 + 2 * tg) =
                    make_float2(acc[nf][0], acc[nf][1]);
                *(float2*)(op + 8 * HID + nf * 8 + 2 * tg) =
                    make_float2(acc[nf][2], acc[nf][3]);
            }
        }
        __syncthreads();   // next iter's cp.async overwrites the buffer just read
    }
}

// ================= LIF kernels (unchanged from R5/R6) ========================
#define L_GROUPS 14
#define GW 64
#define L_THREADS (L_GROUPS * GW)               // 896
#define W_SMEM (HID * HID * 4)                  // 160000 B

__device__ __forceinline__ void group_bar(int grp) {
    asm volatile("bar.sync %0, %1;" :: "r"(grp + 1), "r"(GW) : "memory");
}

__device__ __forceinline__ void scan4(const unsigned* words, const float4* Ws4,
                                      int i, ull& accA, ull& accB) {
    #pragma unroll
    for (int m = 0; m < 8; m++) {
        unsigned u = words[m];
        const int base = ((m >> 2) << 7) + (m & 3);
        while (u) {                                   // uniform among active lanes
            int j = __ffs(u) - 1;
            u &= u - 1;
            int h = base + (j << 2);
            float4 wv = Ws4[h * 50 + i];
            accA = add2(accA, pack2(wv.x, wv.y));
            accB = add2(accB, pack2(wv.z, wv.w));
        }
    }
}

__global__ __launch_bounds__(L_THREADS, 1)
void lif2_kernel(const float* __restrict__ W2, const float* __restrict__ b2) {
    extern __shared__ float smem[];
    const float4* Ws4 = (const float4*)smem;           // [200][50] float4
    __shared__ unsigned sw[2][L_GROUPS][8];
    const int tid = threadIdx.x;
    for (int k = tid; k < HID * HID; k += L_THREADS) smem[k] = W2[k];

    const int  grp  = tid / GW;
    const int  i    = tid - grp * GW;      // 0..63
    const int  lane = i & 31;
    const int  wig  = i >> 5;              // warp in group (0,1)
    const bool iv   = (i < 50);            // active: neurons 4i..4i+3
    float4 bias = make_float4(0.f, 0.f, 0.f, 0.f);
    if (iv) bias = *(const float4*)(b2 + 4 * i);
    __syncthreads();

    for (int b = blockIdx.x * L_GROUPS + grp; b < BATCH; b += gridDim.x * L_GROUPS) {
        float v10 = 0.f, v11 = 0.f, v12 = 0.f, v13 = 0.f;
        float v20 = 0.f, v21 = 0.f, v22 = 0.f, v23 = 0.f;
        const float4* curp = (const float4*)(g_cur + (size_t)b * S_LEN * HID) + (iv ? i : 0);
        unsigned*     spk  = g_spk2 + (size_t)b * S_LEN * 8;

        const int P = 4;
        float4 buf[P];
        #pragma unroll
        for (int q = 0; q < P; q++) buf[q] = iv ? curp[q * 50] : make_float4(0,0,0,0);

        for (int t = 0; t < S_LEN; t++) {
            float4 cur = buf[t & (P - 1)];
            int tp = t + P; if (tp > S_LEN - 1) tp = S_LEN - 1;
            if (iv) buf[t & (P - 1)] = curp[tp * 50];   // prefetch (indep of v)

            v10 = 0.5f * (v10 + cur.x); v11 = 0.5f * (v11 + cur.y);
            v12 = 0.5f * (v12 + cur.z); v13 = 0.5f * (v13 + cur.w);
            bool s0 = iv && (v10 >= 1.0f); if (s0) v10 = 0.f;
            bool s1 = iv && (v11 >= 1.0f); if (s1) v11 = 0.f;
            bool s2 = iv && (v12 >= 1.0f); if (s2) v12 = 0.f;
            bool s3 = iv && (v13 >= 1.0f); if (s3) v13 = 0.f;
            unsigned m0 = __ballot_sync(0xffffffffu, s0);
            unsigned m1 = __ballot_sync(0xffffffffu, s1);
            unsigned m2 = __ballot_sync(0xffffffffu, s2);
            unsigned m3 = __ballot_sync(0xffffffffu, s3);
            if (lane == 0) {
                unsigned* swp = sw[t & 1][grp] + 4 * wig;
                swp[0] = m0; swp[1] = m1; swp[2] = m2; swp[3] = m3;
            }
            group_bar(grp);

            ull accA = pack2(bias.x, bias.y), accB = pack2(bias.z, bias.w);
            if (iv) scan4(sw[t & 1][grp], Ws4, i, accA, accB);
            float a0, a1, a2, a3;
            unpack2(accA, a0, a1); unpack2(accB, a2, a3);

            v20 = 0.5f * (v20 + a0); v21 = 0.5f * (v21 + a1);
            v22 = 0.5f * (v22 + a2); v23 = 0.5f * (v23 + a3);
            bool r0 = iv && (v20 >= 1.0f); if (r0) v20 = 0.f;
            bool r1 = iv && (v21 >= 1.0f); if (r1) v21 = 0.f;
            bool r2 = iv && (v22 >= 1.0f); if (r2) v22 = 0.f;
            bool r3 = iv && (v23 >= 1.0f); if (r3) v23 = 0.f;
            unsigned n0 = __ballot_sync(0xffffffffu, r0);
            unsigned n1 = __ballot_sync(0xffffffffu, r1);
            unsigned n2 = __ballot_sync(0xffffffffu, r2);
            unsigned n3 = __ballot_sync(0xffffffffu, r3);
            if (lane == 0) {
                unsigned* sp = spk + (size_t)t * 8 + 4 * wig;
                sp[0] = n0; sp[1] = n1; sp[2] = n2; sp[3] = n3;
            }
        }
    }
}

__global__ __launch_bounds__(L_THREADS, 1)
void lif3_kernel(const float* __restrict__ W3, const float* __restrict__ b3,
                 const float* __restrict__ Wr, const float* __restrict__ br,
                 float* __restrict__ out) {
    extern __shared__ float smem[];
    const float4* Ws4 = (const float4*)smem;
    __shared__ float cnt_sm[L_GROUPS][HID];
    const int tid = threadIdx.x;
    for (int k = tid; k < HID * HID; k += L_THREADS) smem[k] = W3[k];

    const int  grp  = tid / GW;
    const int  i    = tid - grp * GW;
    const int  lane = i & 31;
    const int  wig  = i >> 5;
    const bool iv   = (i < 50);
    float4 bias = make_float4(0.f, 0.f, 0.f, 0.f);
    if (iv) bias = *(const float4*)(b3 + 4 * i);
    __syncthreads();

    for (int b = blockIdx.x * L_GROUPS + grp; b < BATCH; b += gridDim.x * L_GROUPS) {
        float v30 = 0.f, v31 = 0.f, v32 = 0.f, v33 = 0.f;
        int c0 = 0, c1 = 0, c2 = 0, c3 = 0;
        const unsigned* sp = g_spk2 + (size_t)b * S_LEN * 8;

        unsigned curm[8];
        #pragma unroll
        for (int w = 0; w < 8; w++) curm[w] = __ldg(sp + w);

        for (int t = 0; t < S_LEN; t++) {
            unsigned nxtm[8];
            const unsigned* spn = sp + (size_t)((t + 1 < S_LEN) ? t + 1 : t) * 8;
            #pragma unroll
            for (int w = 0; w < 8; w++) nxtm[w] = __ldg(spn + w);   // prefetch

            ull accA = pack2(bias.x, bias.y), accB = pack2(bias.z, bias.w);
            if (iv) scan4(curm, Ws4, i, accA, accB);
            float a0, a1, a2, a3;
            unpack2(accA, a0, a1); unpack2(accB, a2, a3);

            v30 = 0.5f * (v30 + a0); if (v30 >= 1.0f) { v30 = 0.f; c0++; }
            v31 = 0.5f * (v31 + a1); if (v31 >= 1.0f) { v31 = 0.f; c1++; }
            v32 = 0.5f * (v32 + a2); if (v32 >= 1.0f) { v32 = 0.f; c2++; }
            v33 = 0.5f * (v33 + a3); if (v33 >= 1.0f) { v33 = 0.f; c3++; }
            #pragma unroll
            for (int w = 0; w < 8; w++) curm[w] = nxtm[w];
        }
        if (iv)
            *(float4*)&cnt_sm[grp][4 * i] =
                make_float4((float)c0, (float)c1, (float)c2, (float)c3);
        group_bar(grp);

        if (wig == 0) {                    // warp 0 of group: readout for this b
            float o = -3.0e38f;
            if (lane < DOUT) {
                float acc = 0.f;
                #pragma unroll 4
                for (int k = 0; k < HID; k++)
                    acc += cnt_sm[grp][k] * Wr[k * DOUT + lane];
                o = acc * (1.0f / 101.0f) + br[lane];
            }
            float m = o;
            #pragma unroll
            for (int off = 16; off; off >>= 1)
                m = fmaxf(m, __shfl_xor_sync(0xffffffffu, m, off));
            float e = (lane < DOUT) ? expf(o - m) : 0.f;
            float ssum = e;
            #pragma unroll
            for (int off = 16; off; off >>= 1)
                ssum += __shfl_xor_sync(0xffffffffu, ssum, off);
            if (lane < DOUT) out[b * DOUT + lane] = (o - m) - logf(ssum);
        }
        group_bar(grp);                    // protect cnt_sm before next b iter
    }
}

// ================= launch ====================================================
extern "C" void kernel_launch(void* const* d_in, const int* in_sizes, int n_in,
                              void* d_out, int out_size) {
    const float* x  = (const float*)d_in[0];
    const float* W1 = (const float*)d_in[1];
    const float* b1 = (const float*)d_in[2];
    const float* W2 = (const float*)d_in[3];
    const float* b2 = (const float*)d_in[4];
    const float* W3 = (const float*)d_in[5];
    const float* b3 = (const float*)d_in[6];
    const float* Wr = (const float*)d_in[7];
    const float* br = (const float*)d_in[8];
    float* out = (float*)d_out;

    cudaFuncSetAttribute(gemm1_mma_kernel, cudaFuncAttributeMaxDynamicSharedMemorySize, GM_SMEM);
    cudaFuncSetAttribute(lif2_kernel,      cudaFuncAttributeMaxDynamicSharedMemorySize, W_SMEM);
    cudaFuncSetAttribute(lif3_kernel,      cudaFuncAttributeMaxDynamicSharedMemorySize, W_SMEM);

    const int grid = 148;

    gemm1_mma_kernel<<<grid, GM_THREADS, GM_SMEM>>>(x, W1, b1);
    lif2_kernel    <<<grid, L_THREADS,   W_SMEM>>>(W2, b2);
    lif3_kernel    <<<grid, L_THREADS,   W_SMEM>>>(W3, b3, Wr, br, out);
}